// round 5
// baseline (speedup 1.0000x reference)
#include <cuda_runtime.h>
#include <math.h>

#define Bv 4
#define Cv 64
#define Ov 64
#define Hv 128
#define Wv 128
#define HWv (Hv*Wv)
#define K2 9
#define CO 27

typedef unsigned long long u64;

__device__ __forceinline__ u64 pk2(float a, float b) {
    u64 r; asm("mov.b64 %0, {%1,%2};" : "=l"(r) : "f"(a), "f"(b)); return r;
}
__device__ __forceinline__ void fma2(u64& d, u64 a, u64 b) {
    asm("fma.rn.f32x2 %0, %1, %2, %0;" : "+l"(d) : "l"(a), "l"(b));
}
__device__ __forceinline__ float2 up2(u64 v) {
    float lo, hi; asm("mov.b64 {%0,%1}, %2;" : "=f"(lo), "=f"(hi) : "l"(v));
    return make_float2(lo, hi);
}
__device__ __forceinline__ void bar_sync256(int id) {
    asm volatile("bar.sync %0, 256;" :: "r"(id) : "memory");
}
__device__ __forceinline__ void bar_arrive256(int id) {
    asm volatile("bar.arrive %0, 256;" :: "r"(id) : "memory");
}

#define BFULL0 1
#define BEMPTY0 3

// ---------------- scratch ----------------
__device__ float g_offx[Bv*K2*HWv];
__device__ float g_offy[Bv*K2*HWv];
__device__ float g_mask[Bv*K2*HWv];
__device__ float g_wk[K2*Cv*Ov];   // [k][c][o]

// ---------------- kernel 0: repack w_def [o][c][k] -> [k][c][o] ----------------
__global__ void repack_w_kernel(const float* __restrict__ w_def) {
    int i = blockIdx.x * blockDim.x + threadIdx.x;
    if (i >= K2 * Cv * Ov) return;
    int o = i % Ov;
    int c = (i / Ov) % Cv;
    int k = i / (Ov * Cv);
    g_wk[i] = w_def[(o * Cv + c) * K2 + k];
}

// ---------------- kernel 1: offset conv, channel-chunked, packed weights ----------------
#define CCH 16
#define NCHUNK (Cv/CCH)

__global__ __launch_bounds__(128) void off_conv_kernel(
    const float* __restrict__ feat,
    const float* __restrict__ w_off,
    const float* __restrict__ b_off)
{
    __shared__ float sf[3][CCH][130];      // feat chunk, zero-padded cols
    __shared__ u64   swc2[CCH*9][14];      // weight pairs (co 2q, 2q+1), co27 = 0

    const int h = blockIdx.x;
    const int b = blockIdx.y;
    const int t = threadIdx.x;   // 0..127 == w

    u64 acc[14];
    #pragma unroll
    for (int q = 0; q < 14; q++) {
        float lo = b_off[2*q];
        float hi = (2*q + 1 < CO) ? b_off[2*q + 1] : 0.f;
        acc[q] = pk2(lo, hi);
    }

    for (int chunk = 0; chunk < NCHUNK; chunk++) {
        const int c0 = chunk * CCH;
        __syncthreads();

        for (int i = t; i < CCH*9*14; i += 128) {
            int j = i / 14;
            int q = i % 14;
            float lo = w_off[(2*q) * 576 + c0 * 9 + j];
            float hi = (2*q + 1 < CO) ? w_off[(2*q + 1) * 576 + c0 * 9 + j] : 0.f;
            swc2[j][q] = pk2(lo, hi);
        }
        for (int i = t; i < 3*CCH*130; i += 128) {
            int col = i % 130;
            int cc  = (i / 130) % CCH;
            int r   = i / (130 * CCH);
            int hh = h + r - 1;
            int ww = col - 1;
            float v = 0.f;
            if (hh >= 0 && hh < Hv && ww >= 0 && ww < Wv)
                v = feat[((b * Cv + c0 + cc) * Hv + hh) * Wv + ww];
            (&sf[0][0][0])[i] = v;
        }
        __syncthreads();

        #pragma unroll 2
        for (int cc = 0; cc < CCH; cc++) {
            #pragma unroll
            for (int ky = 0; ky < 3; ky++) {
                #pragma unroll
                for (int kx = 0; kx < 3; kx++) {
                    float f = sf[ky][cc][t + kx];
                    u64 ff = pk2(f, f);
                    const u64* wr = &swc2[cc*9 + ky*3 + kx][0];
                    #pragma unroll
                    for (int q = 0; q < 14; q++)
                        fma2(acc[q], ff, wr[q]);
                }
            }
        }
    }

    float o[28];
    #pragma unroll
    for (int q = 0; q < 14; q++) {
        float2 p = up2(acc[q]);
        o[2*q] = p.x; o[2*q+1] = p.y;
    }

    const int pix = h * Wv + t;
    #pragma unroll
    for (int k = 0; k < K2; k++) {
        int gi = (b * K2 + k) * HWv + pix;
        g_offx[gi] = o[k];
        g_offy[gi] = o[9 + k];
        float m = o[18 + k];
        g_mask[gi] = 1.f / (1.f + __expf(-m));
    }
}

// ---------------- kernel 2: warp-specialized sample + f32x2 GEMM ----------------
// grid (H, B), 256 threads. warps 0-3 sample, warps 4-7 GEMM (w direct from g_wk).
struct Smem2 {
    float v[2][Cv][Wv];       // 64 KB double-buffered sampled tiles
    float offx[K2][Wv];
    float offy[K2][Wv];
    float mask[K2][Wv];       // 13.5 KB
};

__global__ __launch_bounds__(256, 2) void deform_main_kernel(
    const float* __restrict__ x,
    const float* __restrict__ b_def,
    float* __restrict__ out)
{
    extern __shared__ char smem_raw[];
    Smem2& s = *reinterpret_cast<Smem2*>(smem_raw);

    const int h = blockIdx.x;
    const int b = blockIdx.y;
    const int t = threadIdx.x;

    // load offset/mask rows for all 9 taps (all 256 threads)
    for (int i = t; i < K2 * Wv; i += 256) {
        int k  = i >> 7;
        int px = i & 127;
        int gi = (b * K2 + k) * HWv + h * Wv + px;
        s.offx[k][px] = g_offx[gi];
        s.offy[k][px] = g_offy[gi];
        s.mask[k][px] = g_mask[gi];
    }
    __syncthreads();

    if (t < 128) {
        // ================= PRODUCER: bilinear sample =================
        const int px = t;
        const float* xb = x + (size_t)b * Cv * HWv;

        for (int k = 0; k < K2; k++) {
            const int p = k & 1;
            if (k >= 2) bar_sync256(BEMPTY0 + p);

            const int dy = k / 3 - 1;
            const int dx = k % 3 - 1;
            float ys = (float)(h + dy) + s.offy[k][px];
            float xs = (float)(px + dx) + s.offx[k][px];
            float m  = s.mask[k][px];
            float y0f = floorf(ys), x0f = floorf(xs);
            float wy1 = ys - y0f,  wx1 = xs - x0f;
            float wy0 = 1.f - wy1, wx0 = 1.f - wx1;
            int y0 = (int)y0f, x0i = (int)x0f;
            int y1 = y0 + 1,   x1  = x0i + 1;
            float vy0 = (y0 >= 0 && y0 < Hv) ? 1.f : 0.f;
            float vy1 = (y1 >= 0 && y1 < Hv) ? 1.f : 0.f;
            float vx0 = (x0i >= 0 && x0i < Wv) ? 1.f : 0.f;
            float vx1 = (x1 >= 0 && x1 < Wv) ? 1.f : 0.f;
            int y0c = min(max(y0, 0), Hv - 1);
            int y1c = min(max(y1, 0), Hv - 1);
            int x0c = min(max(x0i, 0), Wv - 1);
            int x1c = min(max(x1, 0), Wv - 1);
            float w00 = wy0 * wx0 * vy0 * vx0 * m;
            float w01 = wy0 * wx1 * vy0 * vx1 * m;
            float w10 = wy1 * wx0 * vy1 * vx0 * m;
            float w11 = wy1 * wx1 * vy1 * vx1 * m;
            int i00 = y0c * Wv + x0c;
            int i01 = y0c * Wv + x1c;
            int i10 = y1c * Wv + x0c;
            int i11 = y1c * Wv + x1c;

            #pragma unroll 8
            for (int c = 0; c < Cv; c++) {
                const float* xc = xb + (size_t)c * HWv;
                float val = w00 * __ldg(xc + i00)
                          + w01 * __ldg(xc + i01)
                          + w10 * __ldg(xc + i10)
                          + w11 * __ldg(xc + i11);
                s.v[p][c][px] = val;
            }

            bar_arrive256(BFULL0 + p);      // release: buffer p full
        }
    } else {
        // ================= CONSUMER: f32x2 GEMM, 16o x 4px per thread =================
        const int tc  = t - 128;
        const int o0  = (tc >> 5) * 16;     // warp owns one 16-o group (w LDG warp-uniform)
        const int px0 = (tc & 31) * 4;      // conflict-free v LDS.128

        u64 acc[8][4];                      // o-pair x px
        #pragma unroll
        for (int pp = 0; pp < 8; pp++) {
            u64 bias = pk2(b_def[o0 + 2*pp], b_def[o0 + 2*pp + 1]);
            #pragma unroll
            for (int j = 0; j < 4; j++) acc[pp][j] = bias;
        }

        for (int k = 0; k < K2; k++) {
            const int p = k & 1;
            bar_sync256(BFULL0 + p);        // acquire: buffer p full

            const float4* gw = (const float4*)&g_wk[k * Cv * Ov + o0];

            #pragma unroll 4
            for (int c = 0; c < Cv; c++) {
                // 16 w floats = 8 natural (o,o+1) pairs, warp-uniform LDG (L1-hot)
                float4 wq0 = __ldg(gw + c * 16 + 0);
                float4 wq1 = __ldg(gw + c * 16 + 1);
                float4 wq2 = __ldg(gw + c * 16 + 2);
                float4 wq3 = __ldg(gw + c * 16 + 3);
                u64 w[8];
                w[0] = pk2(wq0.x, wq0.y); w[1] = pk2(wq0.z, wq0.w);
                w[2] = pk2(wq1.x, wq1.y); w[3] = pk2(wq1.z, wq1.w);
                w[4] = pk2(wq2.x, wq2.y); w[5] = pk2(wq2.z, wq2.w);
                w[6] = pk2(wq3.x, wq3.y); w[7] = pk2(wq3.z, wq3.w);

                float4 vv = *(const float4*)&s.v[p][c][px0];
                u64 vd[4];
                vd[0] = pk2(vv.x, vv.x); vd[1] = pk2(vv.y, vv.y);
                vd[2] = pk2(vv.z, vv.z); vd[3] = pk2(vv.w, vv.w);

                #pragma unroll
                for (int pp = 0; pp < 8; pp++) {
                    fma2(acc[pp][0], w[pp], vd[0]);
                    fma2(acc[pp][1], w[pp], vd[1]);
                    fma2(acc[pp][2], w[pp], vd[2]);
                    fma2(acc[pp][3], w[pp], vd[3]);
                }
            }

            bar_arrive256(BEMPTY0 + p);     // buffer p consumed
        }

        // epilogue: ReLU + store (two rows per o-pair)
        #pragma unroll
        for (int pp = 0; pp < 8; pp++) {
            float4 rlo, rhi;
            float2 a0 = up2(acc[pp][0]);
            float2 a1 = up2(acc[pp][1]);
            float2 a2 = up2(acc[pp][2]);
            float2 a3 = up2(acc[pp][3]);
            rlo.x = fmaxf(a0.x, 0.f); rhi.x = fmaxf(a0.y, 0.f);
            rlo.y = fmaxf(a1.x, 0.f); rhi.y = fmaxf(a1.y, 0.f);
            rlo.z = fmaxf(a2.x, 0.f); rhi.z = fmaxf(a2.y, 0.f);
            rlo.w = fmaxf(a3.x, 0.f); rhi.w = fmaxf(a3.y, 0.f);
            float* oplo = &out[((b * Ov + (o0 + 2*pp)) * Hv + h) * Wv + px0];
            float* ophi = &out[((b * Ov + (o0 + 2*pp + 1)) * Hv + h) * Wv + px0];
            *(float4*)oplo = rlo;
            *(float4*)ophi = rhi;
        }
    }
}

// ---------------- launch ----------------
extern "C" void kernel_launch(void* const* d_in, const int* in_sizes, int n_in,
                              void* d_out, int out_size)
{
    const float* x     = (const float*)d_in[0];
    const float* feat  = (const float*)d_in[1];
    const float* w_off = (const float*)d_in[2];
    const float* b_off = (const float*)d_in[3];
    const float* w_def = (const float*)d_in[4];
    const float* b_def = (const float*)d_in[5];
    float* out = (float*)d_out;

    cudaFuncSetAttribute(deform_main_kernel,
                         cudaFuncAttributeMaxDynamicSharedMemorySize, (int)sizeof(Smem2));

    repack_w_kernel<<<(K2 * Cv * Ov + 255) / 256, 256>>>(w_def);
    off_conv_kernel<<<dim3(Hv, Bv), 128>>>(feat, w_off, b_off);
    deform_main_kernel<<<dim3(Hv, Bv), 256, sizeof(Smem2)>>>(x, b_def, out);
}